// round 14
// baseline (speedup 1.0000x reference)
#include <cuda_runtime.h>
#include <cuda_fp16.h>
#include <cstdint>
#include <cstddef>

#define N_NODES 8192
#define IN_DIM  256
#define OUT_DIM 128
#define ALPHA   0.2f
#define MT      32       // rows per CTA
#define KT      64       // j per tile
#define JSPLIT  2        // j-range split across CTAs
#define NTILES_C (N_NODES / KT / JSPLIT)   // 64 tiles per CTA
#define WPR     (N_NODES / 32)   // 256 mask words per row
#define NTHREADS 256

#define WS_STRIDE (KT + 8)       // 72 halves (144B rows, odd 16B multiple)
#define BS_STRIDE (OUT_DIM + 8)  // 136 halves (272B rows, odd 16B multiple)
#define WS_BYTES  (MT * WS_STRIDE * 2)    // 4608
#define BS_BYTES  (KT * BS_STRIDE * 2)    // 17408
#define SMEM_BYTES (2 * WS_BYTES + 2 * BS_BYTES)  // 44032 -> 4+ CTAs/SM

#define WH_BLOCKS (N_NODES / 16)

// Scratch (device globals: no allocation allowed)
__device__ __half   g_Whh [N_NODES * OUT_DIM];
__device__ uint32_t g_abits[N_NODES * WPR];     // 8 MB packed adjacency
__device__ float    g_f1 [N_NODES];
__device__ float    g_f2 [N_NODES];
__device__ uint32_t g_P2 [N_NODES];
__device__ uint32_t g_Q2 [N_NODES];
__device__ __half   g_Uh [N_NODES];
__device__ __half   g_Vh [N_NODES];
__device__ float    g_c;
__device__ float    g_Dp [JSPLIT][N_NODES * OUT_DIM];   // 8 MB partial numerators
__device__ float    g_Sp [JSPLIT][N_NODES];             // partial row sums

// ---------------------------------------------------------------------------
// Kernel 1 (fused): blocks [0,512): Wh = X@W + f1/f2;  rest: bit-pack adjacency.
// ---------------------------------------------------------------------------
__global__ __launch_bounds__(256) void k_pre(const float* __restrict__ X,
                                             const float* __restrict__ W,
                                             const float* __restrict__ a,
                                             const int* __restrict__ adj) {
    const int tid = threadIdx.x;

    if (blockIdx.x >= WH_BLOCKS) {
        const int row  = blockIdx.x - WH_BLOCKS;
        const int w    = tid >> 5;
        const int lane = tid & 31;
        const int4* src4 =
            reinterpret_cast<const int4*>(adj + (size_t)row * N_NODES + w * 1024);
        uint32_t myword = 0;
#pragma unroll
        for (int k = 0; k < 8; k++) {
            int4 v = src4[k * 32 + lane];
            uint32_t nib = (uint32_t)(v.x > 0) | ((uint32_t)(v.y > 0) << 1) |
                           ((uint32_t)(v.z > 0) << 2) | ((uint32_t)(v.w > 0) << 3);
            uint32_t key = nib << ((lane & 7) * 4);
            key |= __shfl_xor_sync(0xffffffffu, key, 1);
            key |= __shfl_xor_sync(0xffffffffu, key, 2);
            key |= __shfl_xor_sync(0xffffffffu, key, 4);
            if ((lane & 7) == k) myword = key;
        }
        g_abits[(size_t)row * WPR + w * 32 + (lane & 7) * 4 + (lane >> 3)] = myword;
        return;
    }

    __shared__ float xs[16][IN_DIM];
    const int i0 = blockIdx.x * 16;

    const float4* Xv  = reinterpret_cast<const float4*>(X + (size_t)i0 * IN_DIM);
    float4*       xsv = reinterpret_cast<float4*>(&xs[0][0]);
#pragma unroll
    for (int q = 0; q < 4; q++) xsv[tid + q * 256] = Xv[tid + q * 256];
    __syncthreads();

    const int cg = tid & 31;
    const int rp = tid >> 5;
    const int r0 = rp * 2, r1 = r0 + 1;
    const int c4 = cg * 4;

    const float4* Wv = reinterpret_cast<const float4*>(W);
    float4 acc0 = {0.f, 0.f, 0.f, 0.f};
    float4 acc1 = {0.f, 0.f, 0.f, 0.f};
#pragma unroll 8
    for (int k = 0; k < IN_DIM; k++) {
        float4 w  = Wv[k * 32 + cg];
        float  x0 = xs[r0][k];
        float  x1 = xs[r1][k];
        acc0.x = fmaf(x0, w.x, acc0.x); acc0.y = fmaf(x0, w.y, acc0.y);
        acc0.z = fmaf(x0, w.z, acc0.z); acc0.w = fmaf(x0, w.w, acc0.w);
        acc1.x = fmaf(x1, w.x, acc1.x); acc1.y = fmaf(x1, w.y, acc1.y);
        acc1.z = fmaf(x1, w.z, acc1.z); acc1.w = fmaf(x1, w.w, acc1.w);
    }
    {
        __half2 h00 = __floats2half2_rn(acc0.x, acc0.y);
        __half2 h01 = __floats2half2_rn(acc0.z, acc0.w);
        __half2 h10 = __floats2half2_rn(acc1.x, acc1.y);
        __half2 h11 = __floats2half2_rn(acc1.z, acc1.w);
        __half2* p0 = reinterpret_cast<__half2*>(g_Whh + (size_t)(i0 + r0) * OUT_DIM + c4);
        __half2* p1 = reinterpret_cast<__half2*>(g_Whh + (size_t)(i0 + r1) * OUT_DIM + c4);
        p0[0] = h00; p0[1] = h01;
        p1[0] = h10; p1[1] = h11;
    }
    float p1 = acc0.x * a[c4] + acc0.y * a[c4 + 1] + acc0.z * a[c4 + 2] + acc0.w * a[c4 + 3];
    float q1 = acc0.x * a[128 + c4] + acc0.y * a[128 + c4 + 1] +
               acc0.z * a[128 + c4 + 2] + acc0.w * a[128 + c4 + 3];
    float p2 = acc1.x * a[c4] + acc1.y * a[c4 + 1] + acc1.z * a[c4 + 2] + acc1.w * a[c4 + 3];
    float q2 = acc1.x * a[128 + c4] + acc1.y * a[128 + c4 + 1] +
               acc1.z * a[128 + c4 + 2] + acc1.w * a[128 + c4 + 3];
#pragma unroll
    for (int off = 16; off; off >>= 1) {
        p1 += __shfl_xor_sync(0xffffffffu, p1, off);
        q1 += __shfl_xor_sync(0xffffffffu, q1, off);
        p2 += __shfl_xor_sync(0xffffffffu, p2, off);
        q2 += __shfl_xor_sync(0xffffffffu, q2, off);
    }
    if (cg == 0) {
        g_f1[i0 + r0] = p1; g_f2[i0 + r0] = q1;
        g_f1[i0 + r1] = p2; g_f2[i0 + r1] = q2;
    }
}

__global__ __launch_bounds__(256) void k_max() {
    __shared__ float red[8];
    int t = threadIdx.x;
    float m = -1e30f;
    for (int i = t; i < N_NODES; i += 256) m = fmaxf(m, g_f2[i]);
#pragma unroll
    for (int off = 16; off; off >>= 1) m = fmaxf(m, __shfl_xor_sync(0xffffffffu, m, off));
    if ((t & 31) == 0) red[t >> 5] = m;
    __syncthreads();
    if (t == 0) {
        float mm = red[0];
#pragma unroll
        for (int i = 1; i < 8; i++) mm = fmaxf(mm, red[i]);
        g_c = mm;
    }
}

__global__ __launch_bounds__(256) void k_prep2() {
    int i = blockIdx.x * 256 + threadIdx.x;
    float f1 = g_f1[i], f2 = g_f2[i], c = g_c;
    float s = f1 + c;
    float M = fmaxf(s, ALPHA * s);
    __half P = __float2half_rn(__expf(f1 - M));
    __half Q = __float2half_rn(__expf(ALPHA * f1 - M));
    uint32_t pu = (uint32_t)__half_as_ushort(P);
    uint32_t qu = (uint32_t)__half_as_ushort(Q);
    g_P2[i] = pu | (pu << 16);
    g_Q2[i] = qu | (qu << 16);
    g_Uh[i] = __float2half_rn(__expf(f2));
    g_Vh[i] = __float2half_rn(__expf(ALPHA * f2));
}

__device__ __forceinline__ uint32_t s2u(const void* p) {
    return (uint32_t)__cvta_generic_to_shared(p);
}
__device__ __forceinline__ void cpasync16(uint32_t dst, const void* src) {
    asm volatile("cp.async.cg.shared.global [%0], [%1], 16;\n" :: "r"(dst), "l"(src));
}
#define CP_COMMIT() asm volatile("cp.async.commit_group;\n" ::: "memory")
#define CP_WAIT0()  asm volatile("cp.async.wait_group 0;\n" ::: "memory")

__device__ __forceinline__ void mma16816(float* d, uint32_t a0, uint32_t a1, uint32_t a2,
                                         uint32_t a3, uint32_t b0, uint32_t b1) {
    asm volatile(
        "mma.sync.aligned.m16n8k16.row.col.f32.f16.f16.f32 "
        "{%0,%1,%2,%3},{%4,%5,%6,%7},{%8,%9},{%0,%1,%2,%3};\n"
        : "+f"(d[0]), "+f"(d[1]), "+f"(d[2]), "+f"(d[3])
        : "r"(a0), "r"(a1), "r"(a2), "r"(a3), "r"(b0), "r"(b1));
}

// generate 8 w-values: w = mask & max(P*U, Q*V); pure half2/ALU; fp32 sum of
// the rounded halves accumulates into Spart (numerator/denominator cancel).
__device__ __forceinline__ void gen8s(uint32_t byte_bits, const __half* Up, const __half* Vp,
                                      uint32_t P2u, uint32_t Q2u, __half* dst,
                                      float& Spart) {
    const uint4 Uv = *reinterpret_cast<const uint4*>(Up);
    const uint4 Vv = *reinterpret_cast<const uint4*>(Vp);
    uint32_t rep = __byte_perm(byte_bits, 0, 0x0000);
    uint32_t m0  = __vcmpne4(rep & 0x08040201u, 0u);
    uint32_t m1  = __vcmpne4(rep & 0x80402010u, 0u);
    const __half2 P2 = *reinterpret_cast<const __half2*>(&P2u);
    const __half2 Q2 = *reinterpret_cast<const __half2*>(&Q2u);
    __half2 w0 = __hmax2(__hmul2(P2, *reinterpret_cast<const __half2*>(&Uv.x)),
                         __hmul2(Q2, *reinterpret_cast<const __half2*>(&Vv.x)));
    __half2 w1 = __hmax2(__hmul2(P2, *reinterpret_cast<const __half2*>(&Uv.y)),
                         __hmul2(Q2, *reinterpret_cast<const __half2*>(&Vv.y)));
    __half2 w2 = __hmax2(__hmul2(P2, *reinterpret_cast<const __half2*>(&Uv.z)),
                         __hmul2(Q2, *reinterpret_cast<const __half2*>(&Vv.z)));
    __half2 w3 = __hmax2(__hmul2(P2, *reinterpret_cast<const __half2*>(&Uv.w)),
                         __hmul2(Q2, *reinterpret_cast<const __half2*>(&Vv.w)));
    uint32_t o0 = *reinterpret_cast<uint32_t*>(&w0) & __byte_perm(m0, 0, 0x1100);
    uint32_t o1 = *reinterpret_cast<uint32_t*>(&w1) & __byte_perm(m0, 0, 0x3322);
    uint32_t o2 = *reinterpret_cast<uint32_t*>(&w2) & __byte_perm(m1, 0, 0x1100);
    uint32_t o3 = *reinterpret_cast<uint32_t*>(&w3) & __byte_perm(m1, 0, 0x3322);
    *reinterpret_cast<uint4*>(dst) = make_uint4(o0, o1, o2, o3);
    float2 c0 = __half22float2(*reinterpret_cast<__half2*>(&o0));
    float2 c1 = __half22float2(*reinterpret_cast<__half2*>(&o1));
    float2 c2 = __half22float2(*reinterpret_cast<__half2*>(&o2));
    float2 c3 = __half22float2(*reinterpret_cast<__half2*>(&o3));
    Spart += ((c0.x + c0.y) + (c1.x + c1.y)) + ((c2.x + c2.y) + (c3.x + c3.y));
}

// ---------------------------------------------------------------------------
// Kernel 3: fused masked-softmax @ Wh partials. Grid 512 = 256 i-blocks x 2
// j-halves; 256 threads, 8 warps (warp tile 16x32), KT=64, ~3.5 CTAs/SM.
// Writes unnormalized D partials + S partials; k_fin combines.
// ---------------------------------------------------------------------------
__global__ __launch_bounds__(NTHREADS, 4) void k_main() {
    extern __shared__ __align__(16) char smem[];
    __half(*WsA[2])[WS_STRIDE];
    __half(*BsA[2])[BS_STRIDE];
    WsA[0] = reinterpret_cast<__half(*)[WS_STRIDE]>(smem);
    WsA[1] = reinterpret_cast<__half(*)[WS_STRIDE]>(smem + WS_BYTES);
    BsA[0] = reinterpret_cast<__half(*)[BS_STRIDE]>(smem + 2 * WS_BYTES);
    BsA[1] = reinterpret_cast<__half(*)[BS_STRIDE]>(smem + 2 * WS_BYTES + BS_BYTES);

    const int tid  = threadIdx.x;
    const int lane = tid & 31, wid = tid >> 5;
    const int wm = wid & 1;        // 2 row-slices of 16
    const int wn = wid >> 1;       // 4 col-slices of 32
    const int ib = blockIdx.x & 255;
    const int jh = blockIdx.x >> 8;        // j-half 0/1
    const int i0 = ib * MT;
    const int j0 = jh * (N_NODES / JSPLIT); // 0 or 4096

    // gen mapping: r = tid>>3 (row 0..31), jo = tid&7 (8 j each)
    const int r  = tid >> 3;
    const int jo = tid & 7;
    // Bs cp.async mapping: 4 threads per j-row (KT=64), 32 halves each
    const int jb = tid >> 2;
    const int bo = (tid & 3) * 32;

    const uint32_t P2u = g_P2[i0 + r];
    const uint32_t Q2u = g_Q2[i0 + r];

    const uint32_t bdst[2] = {s2u(&BsA[0][jb][bo]), s2u(&BsA[1][jb][bo])};
    const __half* bsrc_base = g_Whh + (size_t)(j0 + jb) * OUT_DIM + bo;

    // mask: tile t words start at 2t within this CTA's j-range
    const uint32_t* mrow = g_abits + (size_t)(i0 + r) * WPR + jh * 128 + (jo >> 2);
    const int msh = (jo & 3) * 8;
    const __half* Ubase = g_Uh + j0 + jo * 8;
    const __half* Vbase = g_Vh + j0 + jo * 8;

    float acc[4][4];
#pragma unroll
    for (int n = 0; n < 4; n++)
#pragma unroll
        for (int e = 0; e < 4; e++) acc[n][e] = 0.f;
    float Spart = 0.f;

    // ---- prologue ----
    uint32_t mwA = __ldg(mrow);        // word containing tile-0 byte
    uint32_t mwB = __ldg(mrow + 2);    // tile 1
#pragma unroll
    for (int q = 0; q < 4; q++) cpasync16(bdst[0] + q * 16, bsrc_base + q * 8);
    CP_COMMIT();
    gen8s((mwA >> msh) & 0xffu, Ubase, Vbase, P2u, Q2u, &WsA[0][r][jo * 8], Spart);
    CP_WAIT0();
    __syncthreads();

#pragma unroll 1
    for (int cur = 0; cur < NTILES_C; cur++) {
        const int ph = cur & 1;

        // 1. commit Bs(cur+1)
        if (cur + 1 < NTILES_C) {
            const __half* bsrc = bsrc_base + (size_t)(cur + 1) * KT * OUT_DIM;
#pragma unroll
            for (int q = 0; q < 4; q++) cpasync16(bdst[ph ^ 1] + q * 16, bsrc + q * 8);
            CP_COMMIT();
        }
        // 2. prefetch mask word for tile cur+2
        uint32_t mwC = (cur + 2 < NTILES_C) ? __ldg(mrow + (size_t)(cur + 2) * 2) : 0u;

        // 3. MMA on current buffers (warp tile 16x32, 4 ks)
        __half(*WsC)[WS_STRIDE] = WsA[ph];
        __half(*BsC)[BS_STRIDE] = BsA[ph];
#pragma unroll
        for (int ks = 0; ks < KT / 16; ks++) {
            uint32_t a0, a1, a2, a3;
            uint32_t aaddr = s2u(&WsC[wm * 16 + (lane & 15)][ks * 16 + (lane >> 4) * 8]);
            asm volatile("ldmatrix.sync.aligned.m8n8.x4.shared.b16 {%0,%1,%2,%3}, [%4];"
                         : "=r"(a0), "=r"(a1), "=r"(a2), "=r"(a3)
                         : "r"(aaddr));
#pragma unroll
            for (int h = 0; h < 2; h++) {
                uint32_t b0, b1, b2, b3;
                uint32_t baddr = s2u(&BsC[ks * 16 + (lane & 15)]
                                         [wn * 32 + h * 16 + (lane >> 4) * 8]);
                asm volatile(
                    "ldmatrix.sync.aligned.m8n8.x4.trans.shared.b16 {%0,%1,%2,%3}, [%4];"
                    : "=r"(b0), "=r"(b1), "=r"(b2), "=r"(b3)
                    : "r"(baddr));
                mma16816(acc[h * 2],     a0, a1, a2, a3, b0, b1);
                mma16816(acc[h * 2 + 1], a0, a1, a2, a3, b2, b3);
            }
        }

        // 4. generate next W tile
        if (cur + 1 < NTILES_C)
            gen8s((mwB >> msh) & 0xffu, Ubase + (cur + 1) * KT, Vbase + (cur + 1) * KT,
                  P2u, Q2u, &WsA[ph ^ 1][r][jo * 8], Spart);
        mwB = mwC;

        // 5. single barrier: Bs arrived + gen visible
        CP_WAIT0();
        __syncthreads();
    }

    // ---- epilogue: write S and D partials (no normalization here) ----
    float* Ssum = reinterpret_cast<float*>(smem);
    __syncthreads();
    Ssum[r * 8 + jo] = Spart;
    __syncthreads();
    if (tid < MT) {
        const float4* p = reinterpret_cast<const float4*>(Ssum + tid * 8);
        float4 sa = p[0], sb = p[1];
        g_Sp[jh][i0 + tid] = (sa.x + sa.y + sa.z + sa.w) + (sb.x + sb.y + sb.z + sb.w);
    }

    float* Dp = g_Dp[jh];
    const int g    = lane >> 2;
    const int row0 = wm * 16 + g;
    const int row1 = row0 + 8;
#pragma unroll
    for (int bn = 0; bn < 4; bn++) {
        int cn = wn * 32 + bn * 8 + 2 * (lane & 3);
        size_t o0 = (size_t)(i0 + row0) * OUT_DIM + cn;
        size_t o1 = (size_t)(i0 + row1) * OUT_DIM + cn;
        *reinterpret_cast<float2*>(Dp + o0) = make_float2(acc[bn][0], acc[bn][1]);
        *reinterpret_cast<float2*>(Dp + o1) = make_float2(acc[bn][2], acc[bn][3]);
    }
}

// ---------------------------------------------------------------------------
// Kernel 4: combine partials, softmax scale, ELU. 1M elements, float4 each.
// ---------------------------------------------------------------------------
__global__ __launch_bounds__(256) void k_fin(float* __restrict__ out) {
    int idx4 = blockIdx.x * 256 + threadIdx.x;       // 262144 float4 groups
    int e0 = idx4 * 4;
    int i = e0 >> 7;                                  // node row
    float inv = 1.f / (g_Sp[0][i] + g_Sp[1][i]);
    float4 d0 = *reinterpret_cast<const float4*>(g_Dp[0] + e0);
    float4 d1 = *reinterpret_cast<const float4*>(g_Dp[1] + e0);
    float v0 = (d0.x + d1.x) * inv;
    float v1 = (d0.y + d1.y) * inv;
    float v2 = (d0.z + d1.z) * inv;
    float v3 = (d0.w + d1.w) * inv;
    float4 o;
    o.x = v0 > 0.f ? v0 : __expf(v0) - 1.f;
    o.y = v1 > 0.f ? v1 : __expf(v1) - 1.f;
    o.z = v2 > 0.f ? v2 : __expf(v2) - 1.f;
    o.w = v3 > 0.f ? v3 : __expf(v3) - 1.f;
    *reinterpret_cast<float4*>(out + e0) = o;
}

// ---------------------------------------------------------------------------
extern "C" void kernel_launch(void* const* d_in, const int* in_sizes, int n_in,
                              void* d_out, int out_size) {
    const int*   adj = (const int*)d_in[0];
    const float* X   = (const float*)d_in[1];
    const float* W   = (const float*)d_in[2];
    const float* a   = (const float*)d_in[3];
    float* out = (float*)d_out;

    cudaFuncSetAttribute(k_main, cudaFuncAttributeMaxDynamicSharedMemorySize, SMEM_BYTES);

    k_pre<<<WH_BLOCKS + N_NODES, 256>>>(X, W, a, adj);
    k_max<<<1, 256>>>();
    k_prep2<<<N_NODES / 256, 256>>>();
    k_main<<<(N_NODES / MT) * JSPLIT, NTHREADS, SMEM_BYTES>>>();
    k_fin<<<(N_NODES * OUT_DIM) / (256 * 4), 256>>>(out);
}

// round 15
// speedup vs baseline: 1.5858x; 1.5858x over previous
#include <cuda_runtime.h>
#include <cuda_fp16.h>
#include <cstdint>
#include <cstddef>

#define N_NODES 8192
#define IN_DIM  256
#define OUT_DIM 128
#define ALPHA   0.2f
#define MT      64       // rows per CTA
#define KT      128      // j per tile
#define JSPLIT  2        // j-range split across CTAs
#define NTILES_C (N_NODES / KT / JSPLIT)   // 32 tiles per CTA
#define WPR     (N_NODES / 32)   // 256 mask words per row
#define NTHREADS 512

#define WS_STRIDE (KT + 8)       // 136 halves
#define BS_STRIDE (OUT_DIM + 8)  // 136 halves
#define WS_BYTES  (MT * WS_STRIDE * 2)    // 17408
#define BS_BYTES  (KT * BS_STRIDE * 2)    // 34816
#define SMEM_BYTES (2 * WS_BYTES + 2 * BS_BYTES)  // 104448 -> 2 CTAs/SM

#define WH_BLOCKS (N_NODES / 16)

// Scratch (device globals: no allocation allowed)
__device__ __half   g_Whh [N_NODES * OUT_DIM];
__device__ uint32_t g_abits[N_NODES * WPR];     // 8 MB packed adjacency
__device__ float    g_f1 [N_NODES];
__device__ float    g_f2 [N_NODES];
__device__ uint32_t g_P2 [N_NODES];
__device__ uint32_t g_Q2 [N_NODES];
__device__ __half   g_Uh [N_NODES];
__device__ __half   g_Vh [N_NODES];
__device__ float    g_c;
__device__ float    g_Dp [JSPLIT][N_NODES * OUT_DIM];   // partial numerators
__device__ float    g_Sp [JSPLIT][N_NODES];             // partial row sums

// ---------------------------------------------------------------------------
// Kernel 1 (fused): blocks [0,512): Wh = X@W + f1/f2;  rest: bit-pack adjacency.
// ---------------------------------------------------------------------------
__global__ __launch_bounds__(256) void k_pre(const float* __restrict__ X,
                                             const float* __restrict__ W,
                                             const float* __restrict__ a,
                                             const int* __restrict__ adj) {
    const int tid = threadIdx.x;

    if (blockIdx.x >= WH_BLOCKS) {
        const int row  = blockIdx.x - WH_BLOCKS;
        const int w    = tid >> 5;
        const int lane = tid & 31;
        const int4* src4 =
            reinterpret_cast<const int4*>(adj + (size_t)row * N_NODES + w * 1024);
        uint32_t myword = 0;
#pragma unroll
        for (int k = 0; k < 8; k++) {
            int4 v = src4[k * 32 + lane];
            uint32_t nib = (uint32_t)(v.x > 0) | ((uint32_t)(v.y > 0) << 1) |
                           ((uint32_t)(v.z > 0) << 2) | ((uint32_t)(v.w > 0) << 3);
            uint32_t key = nib << ((lane & 7) * 4);
            key |= __shfl_xor_sync(0xffffffffu, key, 1);
            key |= __shfl_xor_sync(0xffffffffu, key, 2);
            key |= __shfl_xor_sync(0xffffffffu, key, 4);
            if ((lane & 7) == k) myword = key;
        }
        g_abits[(size_t)row * WPR + w * 32 + (lane & 7) * 4 + (lane >> 3)] = myword;
        return;
    }

    __shared__ float xs[16][IN_DIM];
    const int i0 = blockIdx.x * 16;

    const float4* Xv  = reinterpret_cast<const float4*>(X + (size_t)i0 * IN_DIM);
    float4*       xsv = reinterpret_cast<float4*>(&xs[0][0]);
#pragma unroll
    for (int q = 0; q < 4; q++) xsv[tid + q * 256] = Xv[tid + q * 256];
    __syncthreads();

    const int cg = tid & 31;
    const int rp = tid >> 5;
    const int r0 = rp * 2, r1 = r0 + 1;
    const int c4 = cg * 4;

    const float4* Wv = reinterpret_cast<const float4*>(W);
    float4 acc0 = {0.f, 0.f, 0.f, 0.f};
    float4 acc1 = {0.f, 0.f, 0.f, 0.f};
#pragma unroll 8
    for (int k = 0; k < IN_DIM; k++) {
        float4 w  = Wv[k * 32 + cg];
        float  x0 = xs[r0][k];
        float  x1 = xs[r1][k];
        acc0.x = fmaf(x0, w.x, acc0.x); acc0.y = fmaf(x0, w.y, acc0.y);
        acc0.z = fmaf(x0, w.z, acc0.z); acc0.w = fmaf(x0, w.w, acc0.w);
        acc1.x = fmaf(x1, w.x, acc1.x); acc1.y = fmaf(x1, w.y, acc1.y);
        acc1.z = fmaf(x1, w.z, acc1.z); acc1.w = fmaf(x1, w.w, acc1.w);
    }
    {
        __half2 h00 = __floats2half2_rn(acc0.x, acc0.y);
        __half2 h01 = __floats2half2_rn(acc0.z, acc0.w);
        __half2 h10 = __floats2half2_rn(acc1.x, acc1.y);
        __half2 h11 = __floats2half2_rn(acc1.z, acc1.w);
        __half2* p0 = reinterpret_cast<__half2*>(g_Whh + (size_t)(i0 + r0) * OUT_DIM + c4);
        __half2* p1 = reinterpret_cast<__half2*>(g_Whh + (size_t)(i0 + r1) * OUT_DIM + c4);
        p0[0] = h00; p0[1] = h01;
        p1[0] = h10; p1[1] = h11;
    }
    float p1 = acc0.x * a[c4] + acc0.y * a[c4 + 1] + acc0.z * a[c4 + 2] + acc0.w * a[c4 + 3];
    float q1 = acc0.x * a[128 + c4] + acc0.y * a[128 + c4 + 1] +
               acc0.z * a[128 + c4 + 2] + acc0.w * a[128 + c4 + 3];
    float p2 = acc1.x * a[c4] + acc1.y * a[c4 + 1] + acc1.z * a[c4 + 2] + acc1.w * a[c4 + 3];
    float q2 = acc1.x * a[128 + c4] + acc1.y * a[128 + c4 + 1] +
               acc1.z * a[128 + c4 + 2] + acc1.w * a[128 + c4 + 3];
#pragma unroll
    for (int off = 16; off; off >>= 1) {
        p1 += __shfl_xor_sync(0xffffffffu, p1, off);
        q1 += __shfl_xor_sync(0xffffffffu, q1, off);
        p2 += __shfl_xor_sync(0xffffffffu, p2, off);
        q2 += __shfl_xor_sync(0xffffffffu, q2, off);
    }
    if (cg == 0) {
        g_f1[i0 + r0] = p1; g_f2[i0 + r0] = q1;
        g_f1[i0 + r1] = p2; g_f2[i0 + r1] = q2;
    }
}

__global__ __launch_bounds__(256) void k_max() {
    __shared__ float red[8];
    int t = threadIdx.x;
    float m = -1e30f;
    for (int i = t; i < N_NODES; i += 256) m = fmaxf(m, g_f2[i]);
#pragma unroll
    for (int off = 16; off; off >>= 1) m = fmaxf(m, __shfl_xor_sync(0xffffffffu, m, off));
    if ((t & 31) == 0) red[t >> 5] = m;
    __syncthreads();
    if (t == 0) {
        float mm = red[0];
#pragma unroll
        for (int i = 1; i < 8; i++) mm = fmaxf(mm, red[i]);
        g_c = mm;
    }
}

__global__ __launch_bounds__(256) void k_prep2() {
    int i = blockIdx.x * 256 + threadIdx.x;
    float f1 = g_f1[i], f2 = g_f2[i], c = g_c;
    float s = f1 + c;
    float M = fmaxf(s, ALPHA * s);
    __half P = __float2half_rn(__expf(f1 - M));
    __half Q = __float2half_rn(__expf(ALPHA * f1 - M));
    uint32_t pu = (uint32_t)__half_as_ushort(P);
    uint32_t qu = (uint32_t)__half_as_ushort(Q);
    g_P2[i] = pu | (pu << 16);
    g_Q2[i] = qu | (qu << 16);
    g_Uh[i] = __float2half_rn(__expf(f2));
    g_Vh[i] = __float2half_rn(__expf(ALPHA * f2));
}

__device__ __forceinline__ uint32_t s2u(const void* p) {
    return (uint32_t)__cvta_generic_to_shared(p);
}
__device__ __forceinline__ void cpasync16(uint32_t dst, const void* src) {
    asm volatile("cp.async.cg.shared.global [%0], [%1], 16;\n" :: "r"(dst), "l"(src));
}
#define CP_COMMIT() asm volatile("cp.async.commit_group;\n" ::: "memory")
#define CP_WAIT0()  asm volatile("cp.async.wait_group 0;\n" ::: "memory")

__device__ __forceinline__ void mma16816(float* d, uint32_t a0, uint32_t a1, uint32_t a2,
                                         uint32_t a3, uint32_t b0, uint32_t b1) {
    asm volatile(
        "mma.sync.aligned.m16n8k16.row.col.f32.f16.f16.f32 "
        "{%0,%1,%2,%3},{%4,%5,%6,%7},{%8,%9},{%0,%1,%2,%3};\n"
        : "+f"(d[0]), "+f"(d[1]), "+f"(d[2]), "+f"(d[3])
        : "r"(a0), "r"(a1), "r"(a2), "r"(a3), "r"(b0), "r"(b1));
}

// generate 8 w-values: w = mask & max(P*U, Q*V); fp32 sum of rounded halves
// accumulates into Spart (numerator/denominator errors cancel in softmax).
__device__ __forceinline__ void gen8s(uint32_t byte_bits, const __half* Up, const __half* Vp,
                                      uint32_t P2u, uint32_t Q2u, __half* dst,
                                      float& Spart) {
    const uint4 Uv = *reinterpret_cast<const uint4*>(Up);
    const uint4 Vv = *reinterpret_cast<const uint4*>(Vp);
    uint32_t rep = __byte_perm(byte_bits, 0, 0x0000);
    uint32_t m0  = __vcmpne4(rep & 0x08040201u, 0u);
    uint32_t m1  = __vcmpne4(rep & 0x80402010u, 0u);
    const __half2 P2 = *reinterpret_cast<const __half2*>(&P2u);
    const __half2 Q2 = *reinterpret_cast<const __half2*>(&Q2u);
    __half2 w0 = __hmax2(__hmul2(P2, *reinterpret_cast<const __half2*>(&Uv.x)),
                         __hmul2(Q2, *reinterpret_cast<const __half2*>(&Vv.x)));
    __half2 w1 = __hmax2(__hmul2(P2, *reinterpret_cast<const __half2*>(&Uv.y)),
                         __hmul2(Q2, *reinterpret_cast<const __half2*>(&Vv.y)));
    __half2 w2 = __hmax2(__hmul2(P2, *reinterpret_cast<const __half2*>(&Uv.z)),
                         __hmul2(Q2, *reinterpret_cast<const __half2*>(&Vv.z)));
    __half2 w3 = __hmax2(__hmul2(P2, *reinterpret_cast<const __half2*>(&Uv.w)),
                         __hmul2(Q2, *reinterpret_cast<const __half2*>(&Vv.w)));
    uint32_t o0 = *reinterpret_cast<uint32_t*>(&w0) & __byte_perm(m0, 0, 0x1100);
    uint32_t o1 = *reinterpret_cast<uint32_t*>(&w1) & __byte_perm(m0, 0, 0x3322);
    uint32_t o2 = *reinterpret_cast<uint32_t*>(&w2) & __byte_perm(m1, 0, 0x1100);
    uint32_t o3 = *reinterpret_cast<uint32_t*>(&w3) & __byte_perm(m1, 0, 0x3322);
    *reinterpret_cast<uint4*>(dst) = make_uint4(o0, o1, o2, o3);
    float2 c0 = __half22float2(*reinterpret_cast<__half2*>(&o0));
    float2 c1 = __half22float2(*reinterpret_cast<__half2*>(&o1));
    float2 c2 = __half22float2(*reinterpret_cast<__half2*>(&o2));
    float2 c3 = __half22float2(*reinterpret_cast<__half2*>(&o3));
    Spart += ((c0.x + c0.y) + (c1.x + c1.y)) + ((c2.x + c2.y) + (c3.x + c3.y));
}

// ---------------------------------------------------------------------------
// Kernel 3: fused masked-softmax @ Wh partials.
// Grid 256 = 128 i-blocks x 2 j-halves; 512 threads (16 warps, warp tile
// 16x32 over MT=64 x 128), KT=128 -> 32 phases per CTA, 2 CTAs/SM.
// Writes unnormalized D partials + S partials; k_fin combines.
// ---------------------------------------------------------------------------
__global__ __launch_bounds__(NTHREADS, 2) void k_main() {
    extern __shared__ __align__(16) char smem[];
    __half(*WsA[2])[WS_STRIDE];
    __half(*BsA[2])[BS_STRIDE];
    WsA[0] = reinterpret_cast<__half(*)[WS_STRIDE]>(smem);
    WsA[1] = reinterpret_cast<__half(*)[WS_STRIDE]>(smem + WS_BYTES);
    BsA[0] = reinterpret_cast<__half(*)[BS_STRIDE]>(smem + 2 * WS_BYTES);
    BsA[1] = reinterpret_cast<__half(*)[BS_STRIDE]>(smem + 2 * WS_BYTES + BS_BYTES);

    const int tid  = threadIdx.x;
    const int lane = tid & 31, wid = tid >> 5;
    const int wm = wid & 3;        // 4 row-slices of 16
    const int wn = wid >> 2;       // 4 col-slices of 32
    const int ib = blockIdx.x & 127;
    const int jh = blockIdx.x >> 7;          // j-half 0/1
    const int i0 = ib * MT;
    const int j0 = jh * (N_NODES / JSPLIT);  // 0 or 4096

    // gen mapping: r = tid>>3 (row 0..63), jo = tid&7 (two 8-j chunks: jo, jo+8)
    const int r  = tid >> 3;
    const int jo = tid & 7;
    // Bs cp.async mapping: 4 threads per j-row, 32 halves each
    const int jb = tid >> 2;
    const int bo = (tid & 3) * 32;

    const uint32_t P2u = g_P2[i0 + r];
    const uint32_t Q2u = g_Q2[i0 + r];

    const uint32_t bdst[2] = {s2u(&BsA[0][jb][bo]), s2u(&BsA[1][jb][bo])};
    const __half* bsrc_base = g_Whh + (size_t)(j0 + jb) * OUT_DIM + bo;

    // mask: tile t occupies words [t*4, t*4+4) within this j-half
    const uint32_t* mrow = g_abits + (size_t)(i0 + r) * WPR + jh * 128 + (jo >> 2);
    const int msh = (jo & 3) * 8;
    const __half* Ubase = g_Uh + j0 + jo * 8;
    const __half* Vbase = g_Vh + j0 + jo * 8;

    float acc[4][4];
#pragma unroll
    for (int n = 0; n < 4; n++)
#pragma unroll
        for (int e = 0; e < 4; e++) acc[n][e] = 0.f;
    float Spart = 0.f;

    // ---- prologue: tile 0 ----
    uint32_t mwLoA = __ldg(mrow);          // low 64 j of tile 0
    uint32_t mwHiA = __ldg(mrow + 2);      // high 64 j of tile 0
    uint32_t mwLoB = __ldg(mrow + 4);      // tile 1
    uint32_t mwHiB = __ldg(mrow + 6);
#pragma unroll
    for (int q = 0; q < 4; q++) cpasync16(bdst[0] + q * 16, bsrc_base + q * 8);
    CP_COMMIT();
    gen8s((mwLoA >> msh) & 0xffu, Ubase, Vbase, P2u, Q2u, &WsA[0][r][jo * 8], Spart);
    gen8s((mwHiA >> msh) & 0xffu, Ubase + 64, Vbase + 64, P2u, Q2u,
          &WsA[0][r][64 + jo * 8], Spart);
    CP_WAIT0();
    __syncthreads();

#pragma unroll 1
    for (int cur = 0; cur < NTILES_C; cur++) {
        const int ph = cur & 1;

        // 1. commit Bs(cur+1)
        if (cur + 1 < NTILES_C) {
            const __half* bsrc = bsrc_base + (size_t)(cur + 1) * KT * OUT_DIM;
#pragma unroll
            for (int q = 0; q < 4; q++) cpasync16(bdst[ph ^ 1] + q * 16, bsrc + q * 8);
            CP_COMMIT();
        }
        // 2. prefetch mask words for tile cur+2
        uint32_t mwLoC = 0u, mwHiC = 0u;
        if (cur + 2 < NTILES_C) {
            mwLoC = __ldg(mrow + (size_t)(cur + 2) * 4);
            mwHiC = __ldg(mrow + (size_t)(cur + 2) * 4 + 2);
        }

        // 3. MMA on current buffers (warp tile 16x32, 8 ks)
        __half(*WsC)[WS_STRIDE] = WsA[ph];
        __half(*BsC)[BS_STRIDE] = BsA[ph];
#pragma unroll
        for (int ks = 0; ks < KT / 16; ks++) {
            uint32_t a0, a1, a2, a3;
            uint32_t aaddr = s2u(&WsC[wm * 16 + (lane & 15)][ks * 16 + (lane >> 4) * 8]);
            asm volatile("ldmatrix.sync.aligned.m8n8.x4.shared.b16 {%0,%1,%2,%3}, [%4];"
                         : "=r"(a0), "=r"(a1), "=r"(a2), "=r"(a3)
                         : "r"(aaddr));
#pragma unroll
            for (int h = 0; h < 2; h++) {
                uint32_t b0, b1, b2, b3;
                uint32_t baddr = s2u(&BsC[ks * 16 + (lane & 15)]
                                         [wn * 32 + h * 16 + (lane >> 4) * 8]);
                asm volatile(
                    "ldmatrix.sync.aligned.m8n8.x4.trans.shared.b16 {%0,%1,%2,%3}, [%4];"
                    : "=r"(b0), "=r"(b1), "=r"(b2), "=r"(b3)
                    : "r"(baddr));
                mma16816(acc[h * 2],     a0, a1, a2, a3, b0, b1);
                mma16816(acc[h * 2 + 1], a0, a1, a2, a3, b2, b3);
            }
        }

        // 4. generate next W tile
        if (cur + 1 < NTILES_C) {
            const __half* Un = Ubase + (cur + 1) * KT;
            const __half* Vn = Vbase + (cur + 1) * KT;
            gen8s((mwLoB >> msh) & 0xffu, Un, Vn, P2u, Q2u,
                  &WsA[ph ^ 1][r][jo * 8], Spart);
            gen8s((mwHiB >> msh) & 0xffu, Un + 64, Vn + 64, P2u, Q2u,
                  &WsA[ph ^ 1][r][64 + jo * 8], Spart);
        }
        mwLoB = mwLoC; mwHiB = mwHiC;

        // 5. single barrier: Bs arrived + gen visible
        CP_WAIT0();
        __syncthreads();
    }

    // ---- epilogue: write S and D partials (no normalization here) ----
    float* Ssum = reinterpret_cast<float*>(smem);
    __syncthreads();
    Ssum[r * 8 + jo] = Spart;
    __syncthreads();
    if (tid < MT) {
        const float4* p = reinterpret_cast<const float4*>(Ssum + tid * 8);
        float4 sa = p[0], sb = p[1];
        g_Sp[jh][i0 + tid] = (sa.x + sa.y + sa.z + sa.w) + (sb.x + sb.y + sb.z + sb.w);
    }

    float* Dp = g_Dp[jh];
    const int g    = lane >> 2;
    const int row0 = wm * 16 + g;
    const int row1 = row0 + 8;
#pragma unroll
    for (int bn = 0; bn < 4; bn++) {
        int cn = wn * 32 + bn * 8 + 2 * (lane & 3);
        size_t o0 = (size_t)(i0 + row0) * OUT_DIM + cn;
        size_t o1 = (size_t)(i0 + row1) * OUT_DIM + cn;
        *reinterpret_cast<float2*>(Dp + o0) = make_float2(acc[bn][0], acc[bn][1]);
        *reinterpret_cast<float2*>(Dp + o1) = make_float2(acc[bn][2], acc[bn][3]);
    }
}

// ---------------------------------------------------------------------------
// Kernel 4: combine partials, softmax scale, ELU.
// ---------------------------------------------------------------------------
__global__ __launch_bounds__(256) void k_fin(float* __restrict__ out) {
    int idx4 = blockIdx.x * 256 + threadIdx.x;
    int e0 = idx4 * 4;
    int i = e0 >> 7;
    float inv = 1.f / (g_Sp[0][i] + g_Sp[1][i]);
    float4 d0 = *reinterpret_cast<const float4*>(g_Dp[0] + e0);
    float4 d1 = *reinterpret_cast<const float4*>(g_Dp[1] + e0);
    float v0 = (d0.x + d1.x) * inv;
    float v1 = (d0.y + d1.y) * inv;
    float v2 = (d0.z + d1.z) * inv;
    float v3 = (d0.w + d1.w) * inv;
    float4 o;
    o.x = v0 > 0.f ? v0 : __expf(v0) - 1.f;
    o.y = v1 > 0.f ? v1 : __expf(v1) - 1.f;
    o.z = v2 > 0.f ? v2 : __expf(v2) - 1.f;
    o.w = v3 > 0.f ? v3 : __expf(v3) - 1.f;
    *reinterpret_cast<float4*>(out + e0) = o;
}

// ---------------------------------------------------------------------------
extern "C" void kernel_launch(void* const* d_in, const int* in_sizes, int n_in,
                              void* d_out, int out_size) {
    const int*   adj = (const int*)d_in[0];
    const float* X   = (const float*)d_in[1];
    const float* W   = (const float*)d_in[2];
    const float* a   = (const float*)d_in[3];
    float* out = (float*)d_out;

    cudaFuncSetAttribute(k_main, cudaFuncAttributeMaxDynamicSharedMemorySize, SMEM_BYTES);

    k_pre<<<WH_BLOCKS + N_NODES, 256>>>(X, W, a, adj);
    k_max<<<1, 256>>>();
    k_prep2<<<N_NODES / 256, 256>>>();
    k_main<<<(N_NODES / MT) * JSPLIT, NTHREADS, SMEM_BYTES>>>();
    k_fin<<<(N_NODES * OUT_DIM) / (256 * 4), 256>>>(out);
}

// round 17
// speedup vs baseline: 1.6977x; 1.0705x over previous
#include <cuda_runtime.h>
#include <cuda_fp16.h>
#include <cstdint>
#include <cstddef>

#define N_NODES 8192
#define IN_DIM  256
#define OUT_DIM 128
#define ALPHA   0.2f
#define MT      64       // rows per CTA
#define KT      128      // j per tile
#define JSPLIT  4        // j-range split across CTAs
#define NTILES_C (N_NODES / KT / JSPLIT)   // 16 tiles per CTA
#define WPR     (N_NODES / 32)   // 256 mask words per row
#define NTHREADS 512

#define WS_STRIDE (KT + 8)       // 136 halves
#define BS_STRIDE (OUT_DIM + 8)  // 136 halves
#define WS_BYTES  (MT * WS_STRIDE * 2)    // 17408
#define BS_BYTES  (KT * BS_STRIDE * 2)    // 34816
#define SMEM_BYTES (2 * WS_BYTES + 2 * BS_BYTES)  // 104448 -> 2 CTAs/SM

#define WH_BLOCKS (N_NODES / 16)

// Scratch (device globals: no allocation allowed)
__device__ __half   g_Whh [N_NODES * OUT_DIM];
__device__ uint32_t g_abits[N_NODES * WPR];     // 8 MB packed adjacency
__device__ float    g_f1 [N_NODES];
__device__ float    g_f2 [N_NODES];
__device__ uint32_t g_P2 [N_NODES];
__device__ uint32_t g_Q2 [N_NODES];
__device__ __half   g_Uh [N_NODES];
__device__ __half   g_Vh [N_NODES];
__device__ float    g_Dp [JSPLIT][N_NODES * OUT_DIM];   // partial numerators
__device__ float    g_Sp [JSPLIT][N_NODES];             // partial row sums

// ---------------------------------------------------------------------------
// Kernel 1 (fused): blocks [0,8192): pack one adjacency row to bits
// (streaming __ldcs int4 + nibble shfl-reduce; launched FIRST so wave 1 is
// pure DRAM streaming). Blocks [8192,8704): Wh = X@W + f1/f2.
// ---------------------------------------------------------------------------
__global__ __launch_bounds__(256) void k_pre(const float* __restrict__ X,
                                             const float* __restrict__ W,
                                             const float* __restrict__ a,
                                             const int* __restrict__ adj) {
    const int tid = threadIdx.x;

    if (blockIdx.x < N_NODES) {
        const int row  = blockIdx.x;
        const int w    = tid >> 5;
        const int lane = tid & 31;
        const int4* src4 =
            reinterpret_cast<const int4*>(adj + (size_t)row * N_NODES + w * 1024);
        uint32_t myword = 0;
#pragma unroll
        for (int k = 0; k < 8; k++) {
            int4 v = __ldcs(&src4[k * 32 + lane]);   // read-once: evict-first
            uint32_t nib = (uint32_t)(v.x > 0) | ((uint32_t)(v.y > 0) << 1) |
                           ((uint32_t)(v.z > 0) << 2) | ((uint32_t)(v.w > 0) << 3);
            uint32_t key = nib << ((lane & 7) * 4);
            key |= __shfl_xor_sync(0xffffffffu, key, 1);
            key |= __shfl_xor_sync(0xffffffffu, key, 2);
            key |= __shfl_xor_sync(0xffffffffu, key, 4);
            if ((lane & 7) == k) myword = key;
        }
        g_abits[(size_t)row * WPR + w * 32 + (lane & 7) * 4 + (lane >> 3)] = myword;
        return;
    }

    __shared__ float xs[16][IN_DIM];
    const int i0 = (blockIdx.x - N_NODES) * 16;

    const float4* Xv  = reinterpret_cast<const float4*>(X + (size_t)i0 * IN_DIM);
    float4*       xsv = reinterpret_cast<float4*>(&xs[0][0]);
#pragma unroll
    for (int q = 0; q < 4; q++) xsv[tid + q * 256] = Xv[tid + q * 256];
    __syncthreads();

    const int cg = tid & 31;
    const int rp = tid >> 5;
    const int r0 = rp * 2, r1 = r0 + 1;
    const int c4 = cg * 4;

    const float4* Wv = reinterpret_cast<const float4*>(W);
    float4 acc0 = {0.f, 0.f, 0.f, 0.f};
    float4 acc1 = {0.f, 0.f, 0.f, 0.f};
#pragma unroll 8
    for (int k = 0; k < IN_DIM; k++) {
        float4 w  = Wv[k * 32 + cg];
        float  x0 = xs[r0][k];
        float  x1 = xs[r1][k];
        acc0.x = fmaf(x0, w.x, acc0.x); acc0.y = fmaf(x0, w.y, acc0.y);
        acc0.z = fmaf(x0, w.z, acc0.z); acc0.w = fmaf(x0, w.w, acc0.w);
        acc1.x = fmaf(x1, w.x, acc1.x); acc1.y = fmaf(x1, w.y, acc1.y);
        acc1.z = fmaf(x1, w.z, acc1.z); acc1.w = fmaf(x1, w.w, acc1.w);
    }
    {
        __half2 h00 = __floats2half2_rn(acc0.x, acc0.y);
        __half2 h01 = __floats2half2_rn(acc0.z, acc0.w);
        __half2 h10 = __floats2half2_rn(acc1.x, acc1.y);
        __half2 h11 = __floats2half2_rn(acc1.z, acc1.w);
        __half2* p0 = reinterpret_cast<__half2*>(g_Whh + (size_t)(i0 + r0) * OUT_DIM + c4);
        __half2* p1 = reinterpret_cast<__half2*>(g_Whh + (size_t)(i0 + r1) * OUT_DIM + c4);
        p0[0] = h00; p0[1] = h01;
        p1[0] = h10; p1[1] = h11;
    }
    float p1 = acc0.x * a[c4] + acc0.y * a[c4 + 1] + acc0.z * a[c4 + 2] + acc0.w * a[c4 + 3];
    float q1 = acc0.x * a[128 + c4] + acc0.y * a[128 + c4 + 1] +
               acc0.z * a[128 + c4 + 2] + acc0.w * a[128 + c4 + 3];
    float p2 = acc1.x * a[c4] + acc1.y * a[c4 + 1] + acc1.z * a[c4 + 2] + acc1.w * a[c4 + 3];
    float q2 = acc1.x * a[128 + c4] + acc1.y * a[128 + c4 + 1] +
               acc1.z * a[128 + c4 + 2] + acc1.w * a[128 + c4 + 3];
#pragma unroll
    for (int off = 16; off; off >>= 1) {
        p1 += __shfl_xor_sync(0xffffffffu, p1, off);
        q1 += __shfl_xor_sync(0xffffffffu, q1, off);
        p2 += __shfl_xor_sync(0xffffffffu, p2, off);
        q2 += __shfl_xor_sync(0xffffffffu, q2, off);
    }
    if (cg == 0) {
        g_f1[i0 + r0] = p1; g_f2[i0 + r0] = q1;
        g_f1[i0 + r1] = p2; g_f2[i0 + r1] = q2;
    }
}

// ---------------------------------------------------------------------------
// Kernel 2 (merged): each block redundantly computes max_j f2 (8KB read),
// then its 256 nodes' separable softmax factors. Saves a launch + g_c dep.
// ---------------------------------------------------------------------------
__global__ __launch_bounds__(256) void k_maxprep() {
    __shared__ float red[8];
    const int t = threadIdx.x;
    float m = -1e30f;
    for (int i = t; i < N_NODES; i += 256) m = fmaxf(m, g_f2[i]);
#pragma unroll
    for (int off = 16; off; off >>= 1) m = fmaxf(m, __shfl_xor_sync(0xffffffffu, m, off));
    if ((t & 31) == 0) red[t >> 5] = m;
    __syncthreads();
    float c = fmaxf(fmaxf(fmaxf(red[0], red[1]), fmaxf(red[2], red[3])),
                    fmaxf(fmaxf(red[4], red[5]), fmaxf(red[6], red[7])));

    const int i = blockIdx.x * 256 + t;
    float f1 = g_f1[i], f2 = g_f2[i];
    float s = f1 + c;
    float M = fmaxf(s, ALPHA * s);          // >= lrelu(f1+f2_j) for all j
    __half P = __float2half_rn(__expf(f1 - M));
    __half Q = __float2half_rn(__expf(ALPHA * f1 - M));
    uint32_t pu = (uint32_t)__half_as_ushort(P);
    uint32_t qu = (uint32_t)__half_as_ushort(Q);
    g_P2[i] = pu | (pu << 16);
    g_Q2[i] = qu | (qu << 16);
    g_Uh[i] = __float2half_rn(__expf(f2));
    g_Vh[i] = __float2half_rn(__expf(ALPHA * f2));
}

__device__ __forceinline__ uint32_t s2u(const void* p) {
    return (uint32_t)__cvta_generic_to_shared(p);
}
__device__ __forceinline__ void cpasync16(uint32_t dst, const void* src) {
    asm volatile("cp.async.cg.shared.global [%0], [%1], 16;\n" :: "r"(dst), "l"(src));
}
#define CP_COMMIT() asm volatile("cp.async.commit_group;\n" ::: "memory")
#define CP_WAIT0()  asm volatile("cp.async.wait_group 0;\n" ::: "memory")

__device__ __forceinline__ void mma16816(float* d, uint32_t a0, uint32_t a1, uint32_t a2,
                                         uint32_t a3, uint32_t b0, uint32_t b1) {
    asm volatile(
        "mma.sync.aligned.m16n8k16.row.col.f32.f16.f16.f32 "
        "{%0,%1,%2,%3},{%4,%5,%6,%7},{%8,%9},{%0,%1,%2,%3};\n"
        : "+f"(d[0]), "+f"(d[1]), "+f"(d[2]), "+f"(d[3])
        : "r"(a0), "r"(a1), "r"(a2), "r"(a3), "r"(b0), "r"(b1));
}

// generate 8 w-values: w = mask & max(P*U, Q*V); fp32 sum of rounded halves
// accumulates into Spart (numerator/denominator errors cancel in softmax).
__device__ __forceinline__ void gen8s(uint32_t byte_bits, const __half* Up, const __half* Vp,
                                      uint32_t P2u, uint32_t Q2u, __half* dst,
                                      float& Spart) {
    const uint4 Uv = *reinterpret_cast<const uint4*>(Up);
    const uint4 Vv = *reinterpret_cast<const uint4*>(Vp);
    uint32_t rep = __byte_perm(byte_bits, 0, 0x0000);
    uint32_t m0  = __vcmpne4(rep & 0x08040201u, 0u);
    uint32_t m1  = __vcmpne4(rep & 0x80402010u, 0u);
    const __half2 P2 = *reinterpret_cast<const __half2*>(&P2u);
    const __half2 Q2 = *reinterpret_cast<const __half2*>(&Q2u);
    __half2 w0 = __hmax2(__hmul2(P2, *reinterpret_cast<const __half2*>(&Uv.x)),
                         __hmul2(Q2, *reinterpret_cast<const __half2*>(&Vv.x)));
    __half2 w1 = __hmax2(__hmul2(P2, *reinterpret_cast<const __half2*>(&Uv.y)),
                         __hmul2(Q2, *reinterpret_cast<const __half2*>(&Vv.y)));
    __half2 w2 = __hmax2(__hmul2(P2, *reinterpret_cast<const __half2*>(&Uv.z)),
                         __hmul2(Q2, *reinterpret_cast<const __half2*>(&Vv.z)));
    __half2 w3 = __hmax2(__hmul2(P2, *reinterpret_cast<const __half2*>(&Uv.w)),
                         __hmul2(Q2, *reinterpret_cast<const __half2*>(&Vv.w)));
    uint32_t o0 = *reinterpret_cast<uint32_t*>(&w0) & __byte_perm(m0, 0, 0x1100);
    uint32_t o1 = *reinterpret_cast<uint32_t*>(&w1) & __byte_perm(m0, 0, 0x3322);
    uint32_t o2 = *reinterpret_cast<uint32_t*>(&w2) & __byte_perm(m1, 0, 0x1100);
    uint32_t o3 = *reinterpret_cast<uint32_t*>(&w3) & __byte_perm(m1, 0, 0x3322);
    *reinterpret_cast<uint4*>(dst) = make_uint4(o0, o1, o2, o3);
    float2 c0 = __half22float2(*reinterpret_cast<__half2*>(&o0));
    float2 c1 = __half22float2(*reinterpret_cast<__half2*>(&o1));
    float2 c2 = __half22float2(*reinterpret_cast<__half2*>(&o2));
    float2 c3 = __half22float2(*reinterpret_cast<__half2*>(&o3));
    Spart += ((c0.x + c0.y) + (c1.x + c1.y)) + ((c2.x + c2.y) + (c3.x + c3.y));
}

// ---------------------------------------------------------------------------
// Kernel 3: fused masked-softmax @ Wh partials.
// Grid 512 = 128 i-blocks x 4 j-quarters; 512 threads (16 warps, warp tile
// 16x32 over MT=64 x 128), KT=128 -> 16 phases per CTA. Small quanta keep
// all 148 SMs busy (fixes the 108/40 two-CTA imbalance of grid-256).
// ---------------------------------------------------------------------------
__global__ __launch_bounds__(NTHREADS, 2) void k_main() {
    extern __shared__ __align__(16) char smem[];
    __half(*WsA[2])[WS_STRIDE];
    __half(*BsA[2])[BS_STRIDE];
    WsA[0] = reinterpret_cast<__half(*)[WS_STRIDE]>(smem);
    WsA[1] = reinterpret_cast<__half(*)[WS_STRIDE]>(smem + WS_BYTES);
    BsA[0] = reinterpret_cast<__half(*)[BS_STRIDE]>(smem + 2 * WS_BYTES);
    BsA[1] = reinterpret_cast<__half(*)[BS_STRIDE]>(smem + 2 * WS_BYTES + BS_BYTES);

    const int tid  = threadIdx.x;
    const int lane = tid & 31, wid = tid >> 5;
    const int wm = wid & 3;        // 4 row-slices of 16
    const int wn = wid >> 2;       // 4 col-slices of 32
    const int ib = blockIdx.x & 127;
    const int jh = blockIdx.x >> 7;          // j-quarter 0..3
    const int i0 = ib * MT;
    const int j0 = jh * (N_NODES / JSPLIT);  // 0, 2048, 4096, 6144

    // gen mapping: r = tid>>3 (row 0..63), jo = tid&7 (chunks jo and jo+8)
    const int r  = tid >> 3;
    const int jo = tid & 7;
    // Bs cp.async mapping: 4 threads per j-row, 32 halves each
    const int jb = tid >> 2;
    const int bo = (tid & 3) * 32;

    const uint32_t P2u = g_P2[i0 + r];
    const uint32_t Q2u = g_Q2[i0 + r];

    const uint32_t bdst[2] = {s2u(&BsA[0][jb][bo]), s2u(&BsA[1][jb][bo])};
    const __half* bsrc_base = g_Whh + (size_t)(j0 + jb) * OUT_DIM + bo;

    // mask: tile t occupies words [t*4, t*4+4) within this j-quarter (64 words)
    const uint32_t* mrow = g_abits + (size_t)(i0 + r) * WPR +
                           jh * (WPR / JSPLIT) + (jo >> 2);
    const int msh = (jo & 3) * 8;
    const __half* Ubase = g_Uh + j0 + jo * 8;
    const __half* Vbase = g_Vh + j0 + jo * 8;

    float acc[4][4];
#pragma unroll
    for (int n = 0; n < 4; n++)
#pragma unroll
        for (int e = 0; e < 4; e++) acc[n][e] = 0.f;
    float Spart = 0.f;

    // ---- prologue: tile 0 ----
    uint32_t mwLoA = __ldg(mrow);          // low 64 j of tile 0
    uint32_t mwHiA = __ldg(mrow + 2);      // high 64 j of tile 0
    uint32_t mwLoB = __ldg(mrow + 4);      // tile 1
    uint32_t mwHiB = __ldg(mrow + 6);
#pragma unroll
    for (int q = 0; q < 4; q++) cpasync16(bdst[0] + q * 16, bsrc_base + q * 8);
    CP_COMMIT();
    gen8s((mwLoA >> msh) & 0xffu, Ubase, Vbase, P2u, Q2u, &WsA[0][r][jo * 8], Spart);
    gen8s((mwHiA >> msh) & 0xffu, Ubase + 64, Vbase + 64, P2u, Q2u,
          &WsA[0][r][64 + jo * 8], Spart);
    CP_WAIT0();
    __syncthreads();

#pragma unroll 1
    for (int cur = 0; cur < NTILES_C; cur++) {
        const int ph = cur & 1;

        // 1. commit Bs(cur+1)
        if (cur + 1 < NTILES_C) {
            const __half* bsrc = bsrc_base + (size_t)(cur + 1) * KT * OUT_DIM;
#pragma unroll
            for (int q = 0; q < 4; q++) cpasync16(bdst[ph ^ 1] + q * 16, bsrc + q * 8);
            CP_COMMIT();
        }
        // 2. prefetch mask words for tile cur+2
        uint32_t mwLoC = 0u, mwHiC = 0u;
        if (cur + 2 < NTILES_C) {
            mwLoC = __ldg(mrow + (size_t)(cur + 2) * 4);
            mwHiC = __ldg(mrow + (size_t)(cur + 2) * 4 + 2);
        }

        // 3. MMA on current buffers (warp tile 16x32, 8 ks)
        __half(*WsC)[WS_STRIDE] = WsA[ph];
        __half(*BsC)[BS_STRIDE] = BsA[ph];
#pragma unroll
        for (int ks = 0; ks < KT / 16; ks++) {
            uint32_t a0, a1, a2, a3;
            uint32_t aaddr = s2u(&WsC[wm * 16 + (lane & 15)][ks * 16 + (lane >> 4) * 8]);
            asm volatile("ldmatrix.sync.aligned.m8n8.x4.shared.b16 {%0,%1,%2,%3}, [%4];"
                         : "=r"(a0), "=r"(a1), "=r"(a2), "=r"(a3)
                         : "r"(aaddr));
#pragma unroll
            for (int h = 0; h < 2; h++) {
                uint32_t b0, b1, b2, b3;
                uint32_t baddr = s2u(&BsC[ks * 16 + (lane & 15)]
                                         [wn * 32 + h * 16 + (lane >> 4) * 8]);
                asm volatile(
                    "ldmatrix.sync.aligned.m8n8.x4.trans.shared.b16 {%0,%1,%2,%3}, [%4];"
                    : "=r"(b0), "=r"(b1), "=r"(b2), "=r"(b3)
                    : "r"(baddr));
                mma16816(acc[h * 2],     a0, a1, a2, a3, b0, b1);
                mma16816(acc[h * 2 + 1], a0, a1, a2, a3, b2, b3);
            }
        }

        // 4. generate next W tile
        if (cur + 1 < NTILES_C) {
            const __half* Un = Ubase + (cur + 1) * KT;
            const __half* Vn = Vbase + (cur + 1) * KT;
            gen8s((mwLoB >> msh) & 0xffu, Un, Vn, P2u, Q2u,
                  &WsA[ph ^ 1][r][jo * 8], Spart);
            gen8s((mwHiB >> msh) & 0xffu, Un + 64, Vn + 64, P2u, Q2u,
                  &WsA[ph ^ 1][r][64 + jo * 8], Spart);
        }
        mwLoB = mwLoC; mwHiB = mwHiC;

        // 5. single barrier: Bs arrived + gen visible
        CP_WAIT0();
        __syncthreads();
    }

    // ---- epilogue: write S and D partials (no normalization here) ----
    float* Ssum = reinterpret_cast<float*>(smem);
    __syncthreads();
    Ssum[r * 8 + jo] = Spart;
    __syncthreads();
    if (tid < MT) {
        const float4* p = reinterpret_cast<const float4*>(Ssum + tid * 8);
        float4 sa = p[0], sb = p[1];
        g_Sp[jh][i0 + tid] = (sa.x + sa.y + sa.z + sa.w) + (sb.x + sb.y + sb.z + sb.w);
    }

    float* Dp = g_Dp[jh];
    const int g    = lane >> 2;
    const int row0 = wm * 16 + g;
    const int row1 = row0 + 8;
#pragma unroll
    for (int bn = 0; bn < 4; bn++) {
        int cn = wn * 32 + bn * 8 + 2 * (lane & 3);
        size_t o0 = (size_t)(i0 + row0) * OUT_DIM + cn;
        size_t o1 = (size_t)(i0 + row1) * OUT_DIM + cn;
        *reinterpret_cast<float2*>(Dp + o0) = make_float2(acc[bn][0], acc[bn][1]);
        *reinterpret_cast<float2*>(Dp + o1) = make_float2(acc[bn][2], acc[bn][3]);
    }
}

// ---------------------------------------------------------------------------
// Kernel 4: combine 4 partials, softmax scale, ELU.
// ---------------------------------------------------------------------------
__global__ __launch_bounds__(256) void k_fin(float* __restrict__ out) {
    int idx4 = blockIdx.x * 256 + threadIdx.x;
    int e0 = idx4 * 4;
    int i = e0 >> 7;
    float inv = 1.f / (g_Sp[0][i] + g_Sp[1][i] + g_Sp[2][i] + g_Sp[3][i]);
    float4 d0 = *reinterpret_cast<const float4*>(g_Dp[0] + e0);
    float4 d1 = *reinterpret_cast<const float4*>(g_Dp[1] + e0);
    float4 d2 = *reinterpret_cast<const float4*>(g_Dp[2] + e0);
    float4 d3 = *reinterpret_cast<const float4*>(g_Dp[3] + e0);
    float v0 = ((d0.x + d1.x) + (d2.x + d3.x)) * inv;
    float v1 = ((d0.y + d1.y) + (d2.y + d3.y)) * inv;
    float v2 = ((d0.z + d1.z) + (d2.z + d3.z)) * inv;
    float v3 = ((d0.w + d1.w) + (d2.w + d3.w)) * inv;
    float4 o;
    o.x = v0 > 0.f ? v0 : __expf(v0) - 1.f;
    o.y = v1 > 0.f ? v1 : __expf(v1) - 1.f;
    o.z = v2 > 0.f ? v2 : __expf(v2) - 1.f;
    o.w = v3 > 0.f ? v3 : __expf(v3) - 1.f;
    *reinterpret_cast<float4*>(out + e0) = o;
}

// ---------------------------------------------------------------------------
extern "C" void kernel_launch(void* const* d_in, const int* in_sizes, int n_in,
                              void* d_out, int out_size) {
    const int*   adj = (const int*)d_in[0];
    const float* X   = (const float*)d_in[1];
    const float* W   = (const float*)d_in[2];
    const float* a   = (const float*)d_in[3];
    float* out = (float*)d_out;

    cudaFuncSetAttribute(k_main, cudaFuncAttributeMaxDynamicSharedMemorySize, SMEM_BYTES);

    k_pre<<<N_NODES + WH_BLOCKS, 256>>>(X, W, a, adj);
    k_maxprep<<<N_NODES / 256, 256>>>();
    k_main<<<(N_NODES / MT) * JSPLIT, NTHREADS, SMEM_BYTES>>>();
    k_fin<<<(N_NODES * OUT_DIM) / (256 * 4), 256>>>(out);
}